// round 9
// baseline (speedup 1.0000x reference)
#include <cuda_runtime.h>

#define Wd    1024
#define Hd    1024
#define Bd    16
#define RPB   8
#define NBLK2 1024                // blocks; each handles strips b and b+1024
#define TPB   256                 // 256 threads * 4 floats = 1024 = one row

// 1 / (16 * 1024 * 1024) = 2^-24, exact power of two -> exact scaling
#define INV_N 5.9604644775390625e-8f

__global__ void bce_zero_kernel(float* __restrict__ out) {
    if (threadIdx.x == 0) out[0] = 0.0f;
}

__device__ __forceinline__ float4 hmax4(float4 t, float l, float r) {
    float4 h;
    h.x = fmaxf(l,   fmaxf(t.x, t.y));
    h.y = fmaxf(t.x, fmaxf(t.y, t.z));
    h.z = fmaxf(t.y, fmaxf(t.z, t.w));
    h.w = fmaxf(t.z, fmaxf(t.w, r));
    return h;
}

__global__ __launch_bounds__(TPB)
void bce_main_kernel(const float* __restrict__ pred,
                     const float* __restrict__ tgt,
                     float* __restrict__ out) {
    const int x4 = threadIdx.x * 4;        // column of this thread's float4
    const bool has_left  = (x4 > 0);
    const bool has_right = (x4 + 4 < Wd);

    const int r0A = blockIdx.x * RPB;              // strip A first row
    const int r0B = (blockIdx.x + NBLK2) * RPB;    // strip B first row (8 MB away)
    // r0B - r0A = 8192 rows = multiple of Hd -> same row-within-image for both
    const int y0 = r0A & (Hd - 1);

    const float* tA = tgt  + (size_t)r0A * Wd + x4;
    const float* tB = tgt  + (size_t)r0B * Wd + x4;
    const float* pA = pred + (size_t)r0A * Wd + x4;
    const float* pB = pred + (size_t)r0B * Wd + x4;

    // Load one target row (by pointer): raw float4 out-param, returns h-3-max.
    auto load4 = [&](const float* p, float4& t4) -> float4 {
        t4 = *reinterpret_cast<const float4*>(p);
        float l  = has_left  ? __ldg(p - 1) : 0.0f;
        float rr = has_right ? __ldg(p + 4) : 0.0f;
        return hmax4(t4, l, rr);
    };

    const float4 zero4 = make_float4(0.f, 0.f, 0.f, 0.f);
    float4 tdump;

    float4 tcurA, tnextA, hm_m1A, hm_0A, hm_p1A;
    float4 tcurB, tnextB, hm_m1B, hm_0B, hm_p1B;

    if (y0 > 0) {
        hm_m1A = load4(tA - Wd, tdump);
        hm_m1B = load4(tB - Wd, tdump);
    } else {
        hm_m1A = zero4;
        hm_m1B = zero4;
    }
    hm_0A = load4(tA, tcurA);
    hm_0B = load4(tB, tcurB);

    float acc = 0.0f;

    #pragma unroll
    for (int i = 0; i < RPB; ++i) {
        const int y = y0 + i;

        // ---- issue all loads for this iteration first (max MLP) ----
        if (y < Hd - 1) {
            hm_p1A = load4(tA + Wd, tnextA);
            hm_p1B = load4(tB + Wd, tnextB);
        } else {
            hm_p1A = zero4; tnextA = zero4;
            hm_p1B = zero4; tnextB = zero4;
        }
        float4 p4A = *reinterpret_cast<const float4*>(pA);
        float4 p4B = *reinterpret_cast<const float4*>(pB);

        // ---- strip A compute ----
        {
            float dil[4];
            dil[0] = fmaxf(hm_m1A.x, fmaxf(hm_0A.x, hm_p1A.x));
            dil[1] = fmaxf(hm_m1A.y, fmaxf(hm_0A.y, hm_p1A.y));
            dil[2] = fmaxf(hm_m1A.z, fmaxf(hm_0A.z, hm_p1A.z));
            dil[3] = fmaxf(hm_m1A.w, fmaxf(hm_0A.w, hm_p1A.w));
            float tv[4] = {tcurA.x, tcurA.y, tcurA.z, tcurA.w};
            float xv[4] = {p4A.x,   p4A.y,   p4A.z,   p4A.w};
            #pragma unroll
            for (int j = 0; j < 4; ++j) {
                float t = tv[j];
                float x = xv[j];
                float w = (t > 0.5f) ? 20.0f : ((dil[j] > 0.5f) ? 5.0f : 1.0f);
                float a  = fabsf(x);
                float sp = __logf(1.0f + __expf(-a));
                acc = fmaf(w, fmaxf(x, 0.0f) - x * t + sp, acc);
            }
        }
        // ---- strip B compute ----
        {
            float dil[4];
            dil[0] = fmaxf(hm_m1B.x, fmaxf(hm_0B.x, hm_p1B.x));
            dil[1] = fmaxf(hm_m1B.y, fmaxf(hm_0B.y, hm_p1B.y));
            dil[2] = fmaxf(hm_m1B.z, fmaxf(hm_0B.z, hm_p1B.z));
            dil[3] = fmaxf(hm_m1B.w, fmaxf(hm_0B.w, hm_p1B.w));
            float tv[4] = {tcurB.x, tcurB.y, tcurB.z, tcurB.w};
            float xv[4] = {p4B.x,   p4B.y,   p4B.z,   p4B.w};
            #pragma unroll
            for (int j = 0; j < 4; ++j) {
                float t = tv[j];
                float x = xv[j];
                float w = (t > 0.5f) ? 20.0f : ((dil[j] > 0.5f) ? 5.0f : 1.0f);
                float a  = fabsf(x);
                float sp = __logf(1.0f + __expf(-a));
                acc = fmaf(w, fmaxf(x, 0.0f) - x * t + sp, acc);
            }
        }

        // ---- roll windows, march pointers ----
        hm_m1A = hm_0A; hm_0A = hm_p1A; tcurA = tnextA;
        hm_m1B = hm_0B; hm_0B = hm_p1B; tcurB = tnextB;
        tA += Wd; tB += Wd; pA += Wd; pB += Wd;
    }

    // ---- block reduction (fixed tree order), then one relaxed atomic ----
    #pragma unroll
    for (int off = 16; off > 0; off >>= 1)
        acc += __shfl_down_sync(0xffffffffu, acc, off);

    __shared__ float smem[TPB / 32];
    const int lane = threadIdx.x & 31;
    const int wid  = threadIdx.x >> 5;
    if (lane == 0) smem[wid] = acc;
    __syncthreads();
    if (threadIdx.x == 0) {
        acc = smem[0];
        #pragma unroll
        for (int k = 1; k < TPB / 32; ++k) acc += smem[k];
        // exact 2^-24 scale; relaxed fp32 atomic (REDG) — no fence, no acquire
        atomicAdd(out, acc * INV_N);
    }
}

extern "C" void kernel_launch(void* const* d_in, const int* in_sizes, int n_in,
                              void* d_out, int out_size) {
    const float* pred = (const float*)d_in[0];
    const float* tgt  = (const float*)d_in[1];
    float* out = (float*)d_out;

    bce_zero_kernel<<<1, 32>>>(out);
    bce_main_kernel<<<NBLK2, TPB>>>(pred, tgt, out);
}

// round 10
// speedup vs baseline: 1.3825x; 1.3825x over previous
#include <cuda_runtime.h>

#define Wd    1024
#define Hd    1024
#define RPB   8
#define NBLK2 1024                // blocks; each handles strips b and b+1024
#define TPB   256                 // 256 threads * 4 floats = 1024 = one row

// 1 / (16 * 1024 * 1024) = 2^-24, exact power of two -> exact scaling
#define INV_N 5.9604644775390625e-8f

__global__ void bce_zero_kernel(float* __restrict__ out) {
    if (threadIdx.x == 0) out[0] = 0.0f;
}

__device__ __forceinline__ unsigned bits4(float4 t) {
    unsigned m = 0u;
    if (t.x > 0.5f) m |= 1u;
    if (t.y > 0.5f) m |= 2u;
    if (t.z > 0.5f) m |= 4u;
    if (t.w > 0.5f) m |= 8u;
    return m;
}

__global__ __launch_bounds__(TPB)
void bce_main_kernel(const float* __restrict__ pred,
                     const float* __restrict__ tgt,
                     float* __restrict__ out) {
    const int x4   = threadIdx.x * 4;      // column of this thread's float4
    const int lane = threadIdx.x & 31;
    const bool has_left  = (x4 > 0);
    const bool has_right = (x4 + 4 < Wd);

    const int r0A = blockIdx.x * RPB;             // strip A first row
    const int r0B = (blockIdx.x + NBLK2) * RPB;   // strip B, 8 MB away
    // r0B - r0A = 8192 rows = multiple of Hd -> same row-within-image
    const int y0 = r0A & (Hd - 1);

    const float* tA = tgt  + (size_t)r0A * Wd + x4;
    const float* tB = tgt  + (size_t)r0B * Wd + x4;
    const float* pA = pred + (size_t)r0A * Wd + x4;
    const float* pB = pred + (size_t)r0B * Wd + x4;

    // Load one target row -> 4-bit occupancy mask m (out-param) and 4-bit
    // horizontal 3-max mask (return). Neighbor bits via shfl; warp-edge lanes
    // fall back to a scalar L1-hit load.
    auto hrow = [&](const float* p, unsigned& m) -> unsigned {
        float4 t4 = *reinterpret_cast<const float4*>(p);
        m = bits4(t4);
        unsigned ml = __shfl_up_sync(0xffffffffu, m, 1);
        unsigned mr = __shfl_down_sync(0xffffffffu, m, 1);
        unsigned l = (lane == 0)
            ? ((has_left  && __ldg(p - 1) > 0.5f) ? 1u : 0u)
            : ((ml >> 3) & 1u);
        unsigned r = (lane == 31)
            ? ((has_right && __ldg(p + 4) > 0.5f) ? 8u : 0u)
            : ((mr & 1u) << 3);
        return (m | (m << 1) | (m >> 1) | l | r) & 0xFu;
    };

    // rolling 3-row window per strip, 1 int per row
    unsigned hAm1, hA0, hAp1, mA, mnA;
    unsigned hBm1, hB0, hBp1, mB, mnB;
    unsigned dummy;

    if (y0 > 0) {
        hAm1 = hrow(tA - Wd, dummy);
        hBm1 = hrow(tB - Wd, dummy);
    } else {
        hAm1 = 0u; hBm1 = 0u;
    }
    hA0 = hrow(tA, mA);
    hB0 = hrow(tB, mB);

    float acc = 0.0f;

    #pragma unroll
    for (int i = 0; i < RPB; ++i) {
        const int y = y0 + i;

        // ---- issue all loads for this iteration up front (max MLP) ----
        if (y < Hd - 1) {
            hAp1 = hrow(tA + Wd, mnA);
            hBp1 = hrow(tB + Wd, mnB);
        } else {
            hAp1 = 0u; mnA = 0u;
            hBp1 = 0u; mnB = 0u;
        }
        float4 p4A = *reinterpret_cast<const float4*>(pA);
        float4 p4B = *reinterpret_cast<const float4*>(pB);

        const unsigned dilA = hAm1 | hA0 | hAp1;   // vertical max = bit OR
        const unsigned dilB = hBm1 | hB0 | hBp1;

        // ---- strip A ----
        {
            float xs[4] = {p4A.x, p4A.y, p4A.z, p4A.w};
            #pragma unroll
            for (int j = 0; j < 4; ++j) {
                float x = xs[j];
                bool tb = (mA   >> j) & 1u;
                bool db = (dilA >> j) & 1u;
                float w = tb ? 20.0f : (db ? 5.0f : 1.0f);
                float a  = fabsf(x);
                float sp = __logf(1.0f + __expf(-a));   // log1p(exp(-|x|))
                float base = fmaxf(x, 0.0f) - (tb ? x : 0.0f) + sp;
                acc = fmaf(w, base, acc);
            }
        }
        // ---- strip B ----
        {
            float xs[4] = {p4B.x, p4B.y, p4B.z, p4B.w};
            #pragma unroll
            for (int j = 0; j < 4; ++j) {
                float x = xs[j];
                bool tb = (mB   >> j) & 1u;
                bool db = (dilB >> j) & 1u;
                float w = tb ? 20.0f : (db ? 5.0f : 1.0f);
                float a  = fabsf(x);
                float sp = __logf(1.0f + __expf(-a));
                float base = fmaxf(x, 0.0f) - (tb ? x : 0.0f) + sp;
                acc = fmaf(w, base, acc);
            }
        }

        // ---- roll windows, march pointers ----
        hAm1 = hA0; hA0 = hAp1; mA = mnA;
        hBm1 = hB0; hB0 = hBp1; mB = mnB;
        tA += Wd; tB += Wd; pA += Wd; pB += Wd;
    }

    // ---- block reduction (fixed tree order), then one relaxed atomic ----
    #pragma unroll
    for (int off = 16; off > 0; off >>= 1)
        acc += __shfl_down_sync(0xffffffffu, acc, off);

    __shared__ float smem[TPB / 32];
    const int wid = threadIdx.x >> 5;
    if (lane == 0) smem[wid] = acc;
    __syncthreads();
    if (threadIdx.x == 0) {
        acc = smem[0];
        #pragma unroll
        for (int k = 1; k < TPB / 32; ++k) acc += smem[k];
        // exact 2^-24 scale; relaxed fp32 atomic (REDG) — no fence, no acquire
        atomicAdd(out, acc * INV_N);
    }
}

extern "C" void kernel_launch(void* const* d_in, const int* in_sizes, int n_in,
                              void* d_out, int out_size) {
    const float* pred = (const float*)d_in[0];
    const float* tgt  = (const float*)d_in[1];
    float* out = (float*)d_out;

    bce_zero_kernel<<<1, 32>>>(out);
    bce_main_kernel<<<NBLK2, TPB>>>(pred, tgt, out);
}